// round 7
// baseline (speedup 1.0000x reference)
#include <cuda_runtime.h>
#include <math_constants.h>
#include <cstdint>

// WorkingMemory, algebraic form:
//   w_i = e_i*(S-e_i), e_i = exp(attn_i - mx);  ssq = sum e_i^2
//   r{0,1}[b,c] = 2*mx + log( sum_i w_i*exp(m{0,1}[b,i,c]) + exp(v{0,1}[b,c])*ssq )
//
// R7 (= R6 resubmit; prior round was infra timeout):
// Kernel1 = 1184 CTAs (one wave of 148 SM x 8), each owning a contiguous
// fractional range of 65536 16-row units (2048 (b,m) pairs x 32 units).
// Partial linear sums -> static scratch (<=2 CTAs/pair). Kernel2 recomputes
// mx/ssq (deterministic exact max) and finalizes.

#define BB 1024
#define AA 512
#define CC 64
#define DD 10
#define G1 1184            // 148 SMs * 8 CTAs
#define NPAIR (2 * BB)     // 2048
#define UTOT (NPAIR * 32)  // 65536 units; unit = 16 rows of one (b,m) slab

__device__ float g_scratch[NPAIR][2][CC];   // 1 MB static partials

// ---------- reductions over 256 threads ----------
__device__ __forceinline__ float redMax256(float v, float* sbuf) {
    #pragma unroll
    for (int o = 16; o; o >>= 1) v = fmaxf(v, __shfl_xor_sync(0xffffffffu, v, o));
    int w = threadIdx.x >> 5;
    if ((threadIdx.x & 31) == 0) sbuf[w] = v;
    __syncthreads();
    if (threadIdx.x < 32) {
        float x = (threadIdx.x < 8) ? sbuf[threadIdx.x] : -CUDART_INF_F;
        #pragma unroll
        for (int o = 4; o; o >>= 1) x = fmaxf(x, __shfl_xor_sync(0xffffffffu, x, o));
        if (threadIdx.x == 0) sbuf[0] = x;
    }
    __syncthreads();
    float r = sbuf[0];
    __syncthreads();
    return r;
}
__device__ __forceinline__ float redSum256(float v, float* sbuf) {
    #pragma unroll
    for (int o = 16; o; o >>= 1) v += __shfl_xor_sync(0xffffffffu, v, o);
    int w = threadIdx.x >> 5;
    if ((threadIdx.x & 31) == 0) sbuf[w] = v;
    __syncthreads();
    if (threadIdx.x < 32) {
        float x = (threadIdx.x < 8) ? sbuf[threadIdx.x] : 0.0f;
        #pragma unroll
        for (int o = 4; o; o >>= 1) x += __shfl_xor_sync(0xffffffffu, x, o);
        if (threadIdx.x == 0) sbuf[0] = x;
    }
    __syncthreads();
    float r = sbuf[0];
    __syncthreads();
    return r;
}
// ---------- reductions over 512 threads ----------
__device__ __forceinline__ float redMax512(float v, float* sbuf) {
    #pragma unroll
    for (int o = 16; o; o >>= 1) v = fmaxf(v, __shfl_xor_sync(0xffffffffu, v, o));
    int w = threadIdx.x >> 5;
    if ((threadIdx.x & 31) == 0) sbuf[w] = v;
    __syncthreads();
    if (threadIdx.x < 32) {
        float x = (threadIdx.x < 16) ? sbuf[threadIdx.x] : -CUDART_INF_F;
        #pragma unroll
        for (int o = 8; o; o >>= 1) x = fmaxf(x, __shfl_xor_sync(0xffffffffu, x, o));
        if (threadIdx.x == 0) sbuf[0] = x;
    }
    __syncthreads();
    float r = sbuf[0];
    __syncthreads();
    return r;
}
__device__ __forceinline__ float redSum512(float v, float* sbuf) {
    #pragma unroll
    for (int o = 16; o; o >>= 1) v += __shfl_xor_sync(0xffffffffu, v, o);
    int w = threadIdx.x >> 5;
    if ((threadIdx.x & 31) == 0) sbuf[w] = v;
    __syncthreads();
    if (threadIdx.x < 32) {
        float x = (threadIdx.x < 16) ? sbuf[threadIdx.x] : 0.0f;
        #pragma unroll
        for (int o = 8; o; o >>= 1) x += __shfl_xor_sync(0xffffffffu, x, o);
        if (threadIdx.x == 0) sbuf[0] = x;
    }
    __syncthreads();
    float r = sbuf[0];
    __syncthreads();
    return r;
}

// phase 1 with 256 threads: fill sw[512] (weights scaled by exp(-2*mx))
__device__ void phase1_256(int b, const float* __restrict__ a0,
                           const float* __restrict__ a1,
                           float* sw, float* sred) {
    const int tid = threadIdx.x;
    float base = 0.0f, diff[DD];
    const float* pa0 = a0 + b * DD;
    const float* pa1 = a1 + b * DD;
    #pragma unroll
    for (int k = 0; k < DD; k++) {
        float x1 = pa1[k];
        base += x1;
        diff[k] = pa0[k] - x1;
    }
    const int j0 = tid, j1 = tid + 256, j2 = tid + 512, j3 = tid + 768;
    float r0 = base, r1 = base, r2 = base, r3 = base;
    #pragma unroll
    for (int k = 0; k < DD; k++) {
        int sh = 9 - k;
        if ((j0 >> sh) & 1) r0 += diff[k];
        if ((j1 >> sh) & 1) r1 += diff[k];
        if ((j2 >> sh) & 1) r2 += diff[k];
        if ((j3 >> sh) & 1) r3 += diff[k];
    }
    float maxh = redMax256(fmaxf(r2, r3), sred);
    float sumh = redSum256(__expf(r2 - maxh) + __expf(r3 - maxh), sred);
    const float LOG512 = 6.238324625039508f;
    float y2 = maxh + __logf(sumh) - LOG512;

    float ma0 = fmaxf(r0, y2);
    float at0 = ma0 + log1pf(__expf(-fabsf(r0 - y2)));
    float ma1 = fmaxf(r1, y2);
    float at1 = ma1 + log1pf(__expf(-fabsf(r1 - y2)));

    float mx = redMax256(fmaxf(at0, at1), sred);
    float e0 = __expf(at0 - mx);
    float e1 = __expf(at1 - mx);
    float S  = redSum256(e0 + e1, sred);
    sw[j0] = e0 * (S - e0);
    sw[j1] = e1 * (S - e1);
    __syncthreads();
}

__global__ __launch_bounds__(256, 8)
void wm_partial(const float* __restrict__ m0, const float* __restrict__ m1,
                const float* __restrict__ a0, const float* __restrict__ a1)
{
    __shared__ float sred[32];
    __shared__ float sw[AA];
    __shared__ float racc[CC][17];

    const int k   = blockIdx.x;
    const int tid = threadIdx.x;
    const int u0 = (int)(((long long)k * UTOT) / G1);
    const int u1 = (int)(((long long)(k + 1) * UTOT) / G1);
    const int c4 = tid & 15;     // float4 channel block
    const int rg = tid >> 4;     // row-in-unit group, 0..15

    float4 acc = make_float4(0.f, 0.f, 0.f, 0.f);
    int cur_b = -1, cur_p = -1;
    int u = u0;

    while (u < u1) {
        const int p = u >> 5;
        const int b = p >> 1;
        const int m = p & 1;

        if (p != cur_p && cur_p >= 0) {
            // flush cur_p (acc is pre-weighted; does not depend on sw)
            racc[c4 * 4 + 0][rg] = acc.x;
            racc[c4 * 4 + 1][rg] = acc.y;
            racc[c4 * 4 + 2][rg] = acc.z;
            racc[c4 * 4 + 3][rg] = acc.w;
            __syncthreads();
            if (tid < CC) {
                float s = 0.0f;
                #pragma unroll
                for (int g = 0; g < 16; g++) s += racc[tid][g];
                int slot = ((cur_p << 5) < u0) ? 1 : 0;
                g_scratch[cur_p][slot][tid] = s;
                if (slot == 0 && ((cur_p + 1) << 5) <= u1)
                    g_scratch[cur_p][1][tid] = 0.0f;   // unsplit pair: clear slot 1
            }
            __syncthreads();
            acc = make_float4(0.f, 0.f, 0.f, 0.f);
        }
        cur_p = p;
        if (b != cur_b) {
            phase1_256(b, a0, a1, sw, sred);
            cur_b = b;
        }

        const int run      = min(u1, (p + 1) << 5) - u;   // units this pass
        const int base_row = (u & 31) << 4;
        const float4* src  = (const float4*)(m ? m1 : m0)
                             + ((size_t)b << 13) + (base_row << 4) + c4;
        #pragma unroll 4
        for (int j = 0; j < run; j++) {
            const int ro = j * 16 + rg;
            float  w = sw[base_row + ro];
            float4 x = src[ro * 16];
            acc.x = fmaf(w, __expf(x.x), acc.x);
            acc.y = fmaf(w, __expf(x.y), acc.y);
            acc.z = fmaf(w, __expf(x.z), acc.z);
            acc.w = fmaf(w, __expf(x.w), acc.w);
        }
        u += run;
    }

    // final flush
    racc[c4 * 4 + 0][rg] = acc.x;
    racc[c4 * 4 + 1][rg] = acc.y;
    racc[c4 * 4 + 2][rg] = acc.z;
    racc[c4 * 4 + 3][rg] = acc.w;
    __syncthreads();
    if (tid < CC) {
        float s = 0.0f;
        #pragma unroll
        for (int g = 0; g < 16; g++) s += racc[tid][g];
        int slot = ((cur_p << 5) < u0) ? 1 : 0;
        g_scratch[cur_p][slot][tid] = s;
        if (slot == 0 && ((cur_p + 1) << 5) <= u1)
            g_scratch[cur_p][1][tid] = 0.0f;
    }
}

__global__ __launch_bounds__(512)
void wm_final(const float* __restrict__ a0, const float* __restrict__ a1,
              const float* __restrict__ v0, const float* __restrict__ v1,
              float* __restrict__ out)
{
    __shared__ float sred[32];
    const int b   = blockIdx.x;
    const int tid = threadIdx.x;

    float base = 0.0f, diff[DD];
    {
        const float* pa0 = a0 + b * DD;
        const float* pa1 = a1 + b * DD;
        #pragma unroll
        for (int k = 0; k < DD; k++) {
            float x1 = pa1[k];
            base += x1;
            diff[k] = pa0[k] - x1;
        }
    }
    const int jlo = tid, jhi = tid + AA;
    float rlo = base, rhi = base;
    #pragma unroll
    for (int kk = 0; kk < DD; kk++) {
        int sh = 9 - kk;
        if ((jlo >> sh) & 1) rlo += diff[kk];
        if ((jhi >> sh) & 1) rhi += diff[kk];
    }
    float maxh = redMax512(rhi, sred);
    float sumh = redSum512(__expf(rhi - maxh), sred);
    const float LOG512 = 6.238324625039508f;
    float y2 = maxh + __logf(sumh) - LOG512;

    float mab  = fmaxf(rlo, y2);
    float attn = mab + log1pf(__expf(-fabsf(rlo - y2)));

    float mx  = redMax512(attn, sred);
    float e   = __expf(attn - mx);
    float ssq = redSum512(e * e, sred);

    if (tid < 2 * CC) {
        const int mm = tid >> 6;
        const int c  = tid & 63;
        const int p  = b * 2 + mm;
        float s = g_scratch[p][0][c] + g_scratch[p][1][c];
        const float* vv = mm ? v1 : v0;
        float r = 2.0f * mx + __logf(s + __expf(vv[b * CC + c]) * ssq);
        out[(size_t)mm * BB * CC + (size_t)b * CC + c] = r;
    }
}

extern "C" void kernel_launch(void* const* d_in, const int* in_sizes, int n_in,
                              void* d_out, int out_size) {
    const float* m0 = (const float*)d_in[0];
    const float* m1 = (const float*)d_in[1];
    const float* a0 = (const float*)d_in[2];
    const float* a1 = (const float*)d_in[3];
    const float* v0 = (const float*)d_in[4];
    const float* v1 = (const float*)d_in[5];
    float* out = (float*)d_out;
    wm_partial<<<G1, 256>>>(m0, m1, a0, a1);
    wm_final<<<BB, 512>>>(a0, a1, v0, v1, out);
}

// round 14
// speedup vs baseline: 1.1329x; 1.1329x over previous
#include <cuda_runtime.h>
#include <math_constants.h>
#include <cstdint>

// WorkingMemory, uncentered algebraic form (values bounded, fp32-safe):
//   raw[j] = sum_k(bit?a0:a1);  T = (sum_{hi} exp(raw))/512
//   e_i = exp(raw_i) + T;  S = sum e;  ssq = sum e^2
//   r{0,1}[b,c] = log( sum_i e_i*(S-e_i)*exp(m{0,1}[b,i,c]) + exp(v{0,1}[b,c])*ssq )
//
// R14 (= R8 resubmit; R8-R13 were infra timeouts):
// ONE WAVE of 512-thread CTAs (592 = 148x4), fractional contiguous unit
// ranges (unit = 32 rows; 16 units per (b,m) pair; <=2 CTAs per pair).
// Unsplit pairs finalize inline; split pairs (<=591) via scratch + tiny kernel.

#define BB 1024
#define AA 512
#define CC 64
#define DD 10
#define NTH 512
#define G1 592             // 148 SMs * 4 CTAs, one wave
#define NPAIR (2 * BB)     // 2048 (b,m) pairs
#define UPP 16             // units per pair
#define UTOT (NPAIR * UPP) // 32768 units

__device__ float g_part[NPAIR][2][CC];
__device__ float g_ssq[NPAIR];

__device__ __forceinline__ float redSum512(float v, float* sbuf) {
    #pragma unroll
    for (int o = 16; o; o >>= 1) v += __shfl_xor_sync(0xffffffffu, v, o);
    int w = threadIdx.x >> 5;
    if ((threadIdx.x & 31) == 0) sbuf[w] = v;
    __syncthreads();
    if (threadIdx.x < 32) {
        float x = (threadIdx.x < 16) ? sbuf[threadIdx.x] : 0.0f;
        #pragma unroll
        for (int o = 8; o; o >>= 1) x += __shfl_xor_sync(0xffffffffu, x, o);
        if (threadIdx.x == 0) sbuf[0] = x;
    }
    __syncthreads();
    float r = sbuf[0];
    __syncthreads();
    return r;
}

// phase 1, 512 threads: fills sw[512] = e*(S-e), returns ssq. 3 reductions only.
__device__ __forceinline__ void phase1(int b, const float* __restrict__ a0,
                                       const float* __restrict__ a1,
                                       float* sw, float* sred, float& ssq_out) {
    const int tid = threadIdx.x;
    float base = 0.0f, diff[DD];
    const float* pa0 = a0 + b * DD;
    const float* pa1 = a1 + b * DD;
    #pragma unroll
    for (int k = 0; k < DD; k++) {
        float x1 = pa1[k];
        base += x1;
        diff[k] = pa0[k] - x1;
    }
    const int jlo = tid, jhi = tid + AA;
    float rlo = base, rhi = base;
    #pragma unroll
    for (int k = 0; k < DD; k++) {
        int sh = 9 - k;
        if ((jlo >> sh) & 1) rlo += diff[k];
        if ((jhi >> sh) & 1) rhi += diff[k];
    }
    float sumh = redSum512(__expf(rhi), sred);
    float T = sumh * (1.0f / 512.0f);          // exp(y2)
    float e = __expf(rlo) + T;                 // exp(attn_i), no log round-trip
    float S = redSum512(e, sred);
    ssq_out = redSum512(e * e, sred);
    sw[tid] = e * (S - e);
    __syncthreads();
}

__global__ __launch_bounds__(NTH, 4)
void wm_main(const float* __restrict__ m0, const float* __restrict__ m1,
             const float* __restrict__ a0, const float* __restrict__ a1,
             const float* __restrict__ v0, const float* __restrict__ v1,
             float* __restrict__ out)
{
    __shared__ float sred[32];
    __shared__ float sw[AA];
    __shared__ __align__(16) float racc[32][68];   // [row-group][channel], padded

    const int k   = blockIdx.x;
    const int tid = threadIdx.x;
    const int u0 = (int)(((long long)k * UTOT) / G1);
    const int u1 = (int)(((long long)(k + 1) * UTOT) / G1);
    const int c4 = tid & 15;      // float4 channel block (0..15)
    const int rg = tid >> 4;      // row within unit (0..31)

    int cur_b = -1;
    float ssq = 0.0f;
    int u = u0;

    while (u < u1) {
        const int p    = u >> 4;
        const int b    = p >> 1;
        const int m    = p & 1;
        const int pend = (p + 1) << 4;
        const int run  = min(u1, pend) - u;

        if (b != cur_b) { phase1(b, a0, a1, sw, sred, ssq); cur_b = b; }

        const float4* src = (const float4*)(m ? m1 : m0) + ((size_t)b << 13);
        const int row0 = (u & 15) << 5;    // starting row of this span

        float4 acc = make_float4(0.f, 0.f, 0.f, 0.f);
        #pragma unroll 4
        for (int j = 0; j < run; j++) {
            const int row = row0 + j * 32 + rg;
            float  w = sw[row];
            float4 x = src[row * 16 + c4];
            acc.x = fmaf(w, __expf(x.x), acc.x);
            acc.y = fmaf(w, __expf(x.y), acc.y);
            acc.z = fmaf(w, __expf(x.z), acc.z);
            acc.w = fmaf(w, __expf(x.w), acc.w);
        }
        u += run;

        // flush this pair's contribution
        __syncthreads();                       // racc reuse guard
        *reinterpret_cast<float4*>(&racc[rg][c4 * 4]) = acc;
        __syncthreads();

        const bool is_start = (p << 4) >= u0;
        const bool is_end   = (pend <= u1);
        if (tid < CC) {
            float s = 0.0f;
            #pragma unroll
            for (int g = 0; g < 32; g++) s += racc[g][tid];
            if (is_start && is_end) {
                const float* vv = m ? v1 : v0;
                out[((size_t)m * BB + b) * CC + tid] =
                    __logf(s + __expf(vv[b * CC + tid]) * ssq);
            } else if (is_start) {
                g_part[p][0][tid] = s;         // end-CTA's half combined later
            } else {
                g_part[p][1][tid] = s;         // cleanup kernel finalizes
                if (tid == 0) g_ssq[p] = ssq;
            }
        }
    }
}

// finalize the <=591 boundary-split pairs
__global__ __launch_bounds__(64)
void wm_split(const float* __restrict__ v0, const float* __restrict__ v1,
              float* __restrict__ out)
{
    const int k = blockIdx.x + 1;
    const int u0b = (int)(((long long)k * UTOT) / G1);
    if ((u0b & 15) == 0) return;               // boundary aligned: no split pair
    const int p = u0b >> 4;
    const int b = p >> 1;
    const int m = p & 1;
    const int c = threadIdx.x;
    float s = g_part[p][0][c] + g_part[p][1][c];
    float ssq = g_ssq[p];
    const float* vv = m ? v1 : v0;
    out[((size_t)m * BB + b) * CC + c] = __logf(s + __expf(vv[b * CC + c]) * ssq);
}

extern "C" void kernel_launch(void* const* d_in, const int* in_sizes, int n_in,
                              void* d_out, int out_size) {
    const float* m0 = (const float*)d_in[0];
    const float* m1 = (const float*)d_in[1];
    const float* a0 = (const float*)d_in[2];
    const float* a1 = (const float*)d_in[3];
    const float* v0 = (const float*)d_in[4];
    const float* v1 = (const float*)d_in[5];
    float* out = (float*)d_out;
    wm_main<<<G1, NTH>>>(m0, m1, a0, a1, v0, v1, out);
    wm_split<<<G1 - 1, 64>>>(v0, v1, out);
}

// round 15
// speedup vs baseline: 1.1641x; 1.0276x over previous
#include <cuda_runtime.h>
#include <math_constants.h>
#include <cstdint>

// WorkingMemory, uncentered algebraic form (values bounded, fp32-safe):
//   raw[j] = sum_k(bit?a0:a1);  T = (sum_{hi} exp(raw))/512
//   e_i = exp(raw_i) + T;  S = sum e;  ssq = sum e^2
//   r{0,1}[b,c] = log( sum_i e_i*(S-e_i)*exp(m{0,1}[b,i,c]) + exp(v{0,1}[b,c])*ssq )
//
// R15: single kernel. One wave of 512-thread CTAs (592 = 148x4), fractional
// contiguous unit ranges. Unsplit (b,m) pairs finalize inline; boundary-split
// pairs finalize via arrival counter (last-arriver combines; no tail kernel).
// Streaming loads use __ldcs (read-once, evict-first).

#define BB 1024
#define AA 512
#define CC 64
#define DD 10
#define NTH 512
#define G1 592             // 148 SMs * 4 CTAs, one wave
#define NPAIR (2 * BB)     // 2048 (b,m) pairs
#define UTOT (NPAIR * 16)  // 32768 units; unit = 32 rows

__device__ float g_part[NPAIR][2][CC];
__device__ int   g_cnt[NPAIR];          // zero-init; reset after use (replay-safe)

__device__ __forceinline__ float redSum512(float v, float* sbuf) {
    #pragma unroll
    for (int o = 16; o; o >>= 1) v += __shfl_xor_sync(0xffffffffu, v, o);
    int w = threadIdx.x >> 5;
    if ((threadIdx.x & 31) == 0) sbuf[w] = v;
    __syncthreads();
    if (threadIdx.x < 32) {
        float x = (threadIdx.x < 16) ? sbuf[threadIdx.x] : 0.0f;
        #pragma unroll
        for (int o = 8; o; o >>= 1) x += __shfl_xor_sync(0xffffffffu, x, o);
        if (threadIdx.x == 0) sbuf[0] = x;
    }
    __syncthreads();
    float r = sbuf[0];
    __syncthreads();
    return r;
}

// phase 1, 512 threads: fills sw[512] = e*(S-e), returns ssq. 3 reductions only.
__device__ __forceinline__ void phase1(int b, const float* __restrict__ a0,
                                       const float* __restrict__ a1,
                                       float* sw, float* sred, float& ssq_out) {
    const int tid = threadIdx.x;
    float base = 0.0f, diff[DD];
    const float* pa0 = a0 + b * DD;
    const float* pa1 = a1 + b * DD;
    #pragma unroll
    for (int k = 0; k < DD; k++) {
        float x1 = pa1[k];
        base += x1;
        diff[k] = pa0[k] - x1;
    }
    const int jlo = tid, jhi = tid + AA;
    float rlo = base, rhi = base;
    #pragma unroll
    for (int k = 0; k < DD; k++) {
        int sh = 9 - k;
        if ((jlo >> sh) & 1) rlo += diff[k];
        if ((jhi >> sh) & 1) rhi += diff[k];
    }
    float sumh = redSum512(__expf(rhi), sred);
    float T = sumh * (1.0f / 512.0f);          // exp(y2)
    float e = __expf(rlo) + T;                 // exp(attn_i), no log round-trip
    float S = redSum512(e, sred);
    ssq_out = redSum512(e * e, sred);
    sw[tid] = e * (S - e);
    __syncthreads();
}

__global__ __launch_bounds__(NTH, 4)
void wm_main(const float* __restrict__ m0, const float* __restrict__ m1,
             const float* __restrict__ a0, const float* __restrict__ a1,
             const float* __restrict__ v0, const float* __restrict__ v1,
             float* __restrict__ out)
{
    __shared__ float sred[32];
    __shared__ float sw[AA];
    __shared__ __align__(16) float racc[32][68];   // [row-group][channel], padded
    __shared__ int sflag;

    const int k   = blockIdx.x;
    const int tid = threadIdx.x;
    const int u0 = (int)(((long long)k * UTOT) / G1);
    const int u1 = (int)(((long long)(k + 1) * UTOT) / G1);
    const int c4 = tid & 15;      // float4 channel block (0..15)
    const int rg = tid >> 4;      // row within unit (0..31)

    int cur_b = -1;
    float ssq = 0.0f;
    int u = u0;

    while (u < u1) {
        const int p    = u >> 4;
        const int b    = p >> 1;
        const int m    = p & 1;
        const int pend = (p + 1) << 4;
        const int run  = min(u1, pend) - u;

        if (b != cur_b) { phase1(b, a0, a1, sw, sred, ssq); cur_b = b; }

        const float4* src = (const float4*)(m ? m1 : m0) + ((size_t)b << 13);
        const int row0 = (u & 15) << 5;    // starting row of this span

        float4 acc = make_float4(0.f, 0.f, 0.f, 0.f);
        #pragma unroll 4
        for (int j = 0; j < run; j++) {
            const int row = row0 + j * 32 + rg;
            float  w = sw[row];
            float4 x = __ldcs(&src[row * 16 + c4]);   // read-once: evict-first
            acc.x = fmaf(w, __expf(x.x), acc.x);
            acc.y = fmaf(w, __expf(x.y), acc.y);
            acc.z = fmaf(w, __expf(x.z), acc.z);
            acc.w = fmaf(w, __expf(x.w), acc.w);
        }
        u += run;

        // flush this pair's contribution
        __syncthreads();                       // racc reuse guard
        *reinterpret_cast<float4*>(&racc[rg][c4 * 4]) = acc;
        __syncthreads();

        const bool is_start = (p << 4) >= u0;
        const bool is_end   = (pend <= u1);
        if (is_start && is_end) {
            if (tid < CC) {
                float s = 0.0f;
                #pragma unroll
                for (int g = 0; g < 32; g++) s += racc[g][tid];
                const float* vv = m ? v1 : v0;
                out[((size_t)m * BB + b) * CC + tid] =
                    __logf(s + __expf(vv[b * CC + tid]) * ssq);
            }
        } else {
            // boundary-split pair: partial to scratch, last arriver finalizes
            if (tid < CC) {
                float s = 0.0f;
                #pragma unroll
                for (int g = 0; g < 32; g++) s += racc[g][tid];
                g_part[p][is_start ? 0 : 1][tid] = s;
            }
            __threadfence();                   // release partials
            __syncthreads();
            if (tid == 0) sflag = atomicAdd(&g_cnt[p], 1);
            __syncthreads();
            if (sflag == 1) {                  // both halves present
                __threadfence();               // acquire partner's partials
                if (tid < CC) {
                    float s = g_part[p][0][tid] + g_part[p][1][tid];
                    const float* vv = m ? v1 : v0;
                    out[((size_t)m * BB + b) * CC + tid] =
                        __logf(s + __expf(vv[b * CC + tid]) * ssq);
                }
                __syncthreads();
                if (tid == 0) g_cnt[p] = 0;    // reset for next graph replay
            }
        }
    }
}

extern "C" void kernel_launch(void* const* d_in, const int* in_sizes, int n_in,
                              void* d_out, int out_size) {
    const float* m0 = (const float*)d_in[0];
    const float* m1 = (const float*)d_in[1];
    const float* a0 = (const float*)d_in[2];
    const float* a1 = (const float*)d_in[3];
    const float* v0 = (const float*)d_in[4];
    const float* v1 = (const float*)d_in[5];
    float* out = (float*)d_out;
    wm_main<<<G1, NTH>>>(m0, m1, a0, a1, v0, v1, out);
}